// round 16
// baseline (speedup 1.0000x reference)
#include <cuda_runtime.h>
#include <cuda_bf16.h>
#include <math.h>

#define NLAYERS 40
#define TB 128
#define NT 256

// hi/lo interleaved 16B slots: [hi 8B | lo 8B] per (row, kchunk, tg)
// strides % 128 == 64 -> conflict-free 16B fragment loads (quarter-warp disjoint)
#define SA_STRIDE 576      // A rows: 8 chunks x 64B
#define SW1_STRIDE 576     // W1 rows: same
#define SW2_STRIDE 320     // W2 rows: 4 chunks x 64B

// smem layout (bytes)
#define OFF_A    0                  // 128*576 = 73728
#define OFF_W    73728              // weight region 40960 (W1 36864 or 2 W2 chunks 40960)
#define OFF_BIAS 114688             // 192 f32
#define SMEM_BYTES 115456

#define W1_BYTES 36864              // 64*576
#define W2_CHUNK_BYTES 20480        // 64*320
#define W2_BYTES 61440              // 192*320

// ---------------- global scratch ----------------
__device__ float g_buf0[8 * 64 * 8192];
__device__ float g_buf1[8 * 64 * 8192];
__device__ __align__(16) unsigned char g_w1img[NLAYERS * W1_BYTES];
__device__ __align__(16) unsigned char g_w2img[NLAYERS * W2_BYTES];
__device__ float g_bias[NLAYERS * 192];

// ---------------- helpers ----------------
__device__ __forceinline__ void mma_bf16(float* c, const unsigned* a, const unsigned* b) {
    asm volatile(
        "mma.sync.aligned.m16n8k16.row.col.f32.bf16.bf16.f32 "
        "{%0,%1,%2,%3}, {%4,%5,%6,%7}, {%8,%9}, {%0,%1,%2,%3};"
        : "+f"(c[0]), "+f"(c[1]), "+f"(c[2]), "+f"(c[3])
        : "r"(a[0]), "r"(a[1]), "r"(a[2]), "r"(a[3]), "r"(b[0]), "r"(b[1]));
}

__device__ __forceinline__ void split2(float a, float b, unsigned& hi, unsigned& lo) {
    __nv_bfloat16 ha = __float2bfloat16(a), hb = __float2bfloat16(b);
    float la = a - __bfloat162float(ha);
    float lb = b - __bfloat162float(hb);
    hi = ((unsigned)__bfloat16_as_ushort(hb) << 16) | (unsigned)__bfloat16_as_ushort(ha);
    __nv_bfloat16 bla = __float2bfloat16(la), blb = __float2bfloat16(lb);
    lo = ((unsigned)__bfloat16_as_ushort(blb) << 16) | (unsigned)__bfloat16_as_ushort(bla);
}

__device__ __forceinline__ float gate_fn(float y) {
    float ay = fabsf(y);
    float e1 = __expf(-ay);
    float e2 = e1 * e1;
    float th = __fdividef(1.f - e2, 1.f + e2);
    float sp = __fdividef(1.f, 1.f + e1);
    float sig = (y >= 0.f) ? sp : (1.f - sp);
    return copysignf(th, y) * sig;
}

// element col -> byte offset of its HI bf16 within the row image
__device__ __forceinline__ unsigned ilv3(unsigned col) {
    unsigned e = col & 15;
    unsigned t = (e & 7) >> 1;
    return (col >> 4) * 64 + t * 16 + (e >> 3) * 4 + (e & 1) * 2;
}

// ------------------------- weight repack -------------------------
#define RN1 (NLAYERS * 64 * 64 * 2)
#define RN2 (NLAYERS * 64 * 64)
#define RN3 (NLAYERS * 128 * 64)
#define RN4 (NLAYERS * 64)
#define RN5 (NLAYERS * 128)
#define RNTOT (RN1 + RN2 + RN3 + RN4 + RN5)

__global__ void repack_kernel(const float* __restrict__ wd, const float* __restrict__ wr,
                              const float* __restrict__ br, const float* __restrict__ ws,
                              const float* __restrict__ bs) {
    int idx = blockIdx.x * blockDim.x + threadIdx.x;
    if (idx < RN1) {  // w_dil[l][o][i][k] -> W1 row o, col k*64+i
        float v = wd[idx];
        int k = idx & 1, i = (idx >> 1) & 63, o = (idx >> 7) & 63, l = idx >> 13;
        __nv_bfloat16 h = __float2bfloat16(v);
        __nv_bfloat16 lo = __float2bfloat16(v - __bfloat162float(h));
        unsigned byte = (unsigned)o * SW1_STRIDE + ilv3((unsigned)(k * 64 + i));
        *(__nv_bfloat16*)(g_w1img + (size_t)l * W1_BYTES + byte) = h;
        *(__nv_bfloat16*)(g_w1img + (size_t)l * W1_BYTES + byte + 8) = lo;
        return;
    }
    idx -= RN1;
    if (idx < RN2) {  // w_res[l][o][i] -> W2 row o
        float v = wr[idx];
        int i = idx & 63, o = (idx >> 6) & 63, l = idx >> 12;
        __nv_bfloat16 h = __float2bfloat16(v);
        __nv_bfloat16 lo = __float2bfloat16(v - __bfloat162float(h));
        unsigned byte = (unsigned)o * SW2_STRIDE + ilv3((unsigned)i);
        *(__nv_bfloat16*)(g_w2img + (size_t)l * W2_BYTES + byte) = h;
        *(__nv_bfloat16*)(g_w2img + (size_t)l * W2_BYTES + byte + 8) = lo;
        return;
    }
    idx -= RN2;
    if (idx < RN3) {  // w_skip[l][o][i] -> W2 row 64+o
        float v = ws[idx];
        int i = idx & 63, o = (idx >> 6) & 127, l = idx >> 13;
        __nv_bfloat16 h = __float2bfloat16(v);
        __nv_bfloat16 lo = __float2bfloat16(v - __bfloat162float(h));
        unsigned byte = (unsigned)(64 + o) * SW2_STRIDE + ilv3((unsigned)i);
        *(__nv_bfloat16*)(g_w2img + (size_t)l * W2_BYTES + byte) = h;
        *(__nv_bfloat16*)(g_w2img + (size_t)l * W2_BYTES + byte + 8) = lo;
        return;
    }
    idx -= RN3;
    if (idx < RN4) { int o = idx & 63, l = idx >> 6; g_bias[l * 192 + o] = br[idx]; return; }
    idx -= RN4;
    if (idx < RN5) { int o = idx & 127, l = idx >> 7; g_bias[l * 192 + 64 + o] = bs[idx]; return; }
}

// ------------------------- fused mma.sync layer kernel -------------------------
// CTA: 128 timesteps x one batch. 8 warps; warp w owns rows 16w..16w+15.
__global__ __launch_bounds__(NT, 2) void layer_kernel(
    const float* __restrict__ src, float* __restrict__ dst,
    const unsigned char* __restrict__ w1img, const unsigned char* __restrict__ w2img,
    const float* __restrict__ bias, float* __restrict__ skipOut,
    int d, int L, int nTiles) {
    extern __shared__ unsigned char smem[];
    const int tid = threadIdx.x;
    const int lane = tid & 31;
    const int w = tid >> 5;
    const int b = blockIdx.y;
    const int t0 = L - (nTiles - blockIdx.x) * TB;
    const int Tin = L + d;

    // ---- stage W1 (2304 uint4) + bias ----
    {
        const uint4* g1 = (const uint4*)w1img;
        uint4* s1 = (uint4*)(smem + OFF_W);
#pragma unroll
        for (int k = 0; k < 9; k++) s1[tid + NT * k] = g1[tid + NT * k];
        float* sBias = (float*)(smem + OFF_BIAS);
        if (tid < 192) sBias[tid] = bias[tid];
    }

    // ---- stage A: thread = (row, tap). Coalesced gmem loads, interleaved hi/lo scatter ----
    const float* srcB = src + (size_t)b * 64 * 8192;
    {
        const int row = tid & 127;
        const int tap = tid >> 7;
        const int sh = tap ? d : 0;
        int g = t0 + row + sh;
        g = min(max(g, 0), Tin - 1);
        const float* colp = srcB + g;
        unsigned rowb = (unsigned)row * SA_STRIDE;
#pragma unroll
        for (int cc = 0; cc < 4; cc++) {
            float v[16];
#pragma unroll
            for (int e = 0; e < 16; e++) v[e] = colp[(size_t)(cc * 16 + e) * 8192];
            unsigned addr0 = rowb + (unsigned)(tap * 4 + cc) * 64;
#pragma unroll
            for (int t = 0; t < 4; t++) {
                unsigned h0, l0, h1, l1;
                split2(v[2 * t], v[2 * t + 1], h0, l0);
                split2(v[2 * t + 8], v[2 * t + 9], h1, l1);
                *(uint4*)(smem + OFF_A + addr0 + t * 16) = make_uint4(h0, h1, l0, l1);
            }
        }
    }
    __syncthreads();

    const int tg = lane & 3;
    const int rfrag = lane >> 2;

    // ---------------- phase 1: y = A @ W1^T (3-split bf16, hoisted B + term rounds) ----------------
    float acc[8][4];
#pragma unroll
    for (int nn = 0; nn < 8; nn++)
#pragma unroll
        for (int q = 0; q < 4; q++) acc[nn][q] = 0.f;

#pragma unroll 1
    for (int kk = 0; kk < 8; kk++) {
        unsigned ra = (unsigned)(w * 16 + rfrag) * SA_STRIDE + (unsigned)kk * 64 + (unsigned)tg * 16;
        uint4 u = *(const uint4*)(smem + OFF_A + ra);
        uint4 vv = *(const uint4*)(smem + OFF_A + ra + 8 * SA_STRIDE);
        unsigned ah[4] = {u.x, vv.x, u.y, vv.y};
        unsigned al[4] = {u.z, vv.z, u.w, vv.w};
        uint4 bb[8];
#pragma unroll
        for (int nn = 0; nn < 8; nn++) {
            unsigned nb = (unsigned)(nn * 8 + rfrag) * SW1_STRIDE + (unsigned)kk * 64 + (unsigned)tg * 16;
            bb[nn] = *(const uint4*)(smem + OFF_W + nb);
        }
#pragma unroll
        for (int nn = 0; nn < 8; nn++) {
            unsigned bh[2] = {bb[nn].x, bb[nn].y};
            mma_bf16(acc[nn], ah, bh);
        }
#pragma unroll
        for (int nn = 0; nn < 8; nn++) {
            unsigned bh[2] = {bb[nn].x, bb[nn].y};
            mma_bf16(acc[nn], al, bh);
        }
#pragma unroll
        for (int nn = 0; nn < 8; nn++) {
            unsigned bl[2] = {bb[nn].z, bb[nn].w};
            mma_bf16(acc[nn], ah, bl);
        }
    }

    // ---------------- gate -> phase2 A fragments (registers only) ----------------
    unsigned gh[4][4], gl[4][4];
#pragma unroll
    for (int kt = 0; kt < 4; kt++) {
        int n0 = 2 * kt, n1 = 2 * kt + 1;
        split2(gate_fn(acc[n0][0]), gate_fn(acc[n0][1]), gh[kt][0], gl[kt][0]);
        split2(gate_fn(acc[n0][2]), gate_fn(acc[n0][3]), gh[kt][1], gl[kt][1]);
        split2(gate_fn(acc[n1][0]), gate_fn(acc[n1][1]), gh[kt][2], gl[kt][2]);
        split2(gate_fn(acc[n1][2]), gate_fn(acc[n1][3]), gh[kt][3], gl[kt][3]);
    }

    // ---------------- phase 2: [res | skip] = G @ W2^T ----------------
    const int skipOff = L - 4096;
    const bool needSkip = (t0 + TB > skipOff);
    const int nch = needSkip ? 3 : 1;
    const float* sBias = (const float*)(smem + OFF_BIAS);
    const uint4* w2g = (const uint4*)w2img;
    uint4* sw = (uint4*)(smem + OFF_W);

    for (int c = 0; c < nch; c++) {
        if (c == 0) {
            __syncthreads();   // done reading W1
            int nu4 = needSkip ? 2560 : 1280;   // chunks 0 (+1)
            for (int i = tid; i < nu4; i += NT) sw[i] = w2g[i];
            __syncthreads();
        } else if (c == 2) {
            __syncthreads();   // done reading chunks 0/1
            for (int i = tid; i < 1280; i += NT) sw[i] = w2g[2560 + i];
            __syncthreads();
        }
        const unsigned wb = OFF_W + ((c == 1) ? (unsigned)W2_CHUNK_BYTES : 0u);

        float acc2[8][4];
#pragma unroll
        for (int nn = 0; nn < 8; nn++)
#pragma unroll
            for (int q = 0; q < 4; q++) acc2[nn][q] = 0.f;

#pragma unroll 1
        for (int kt = 0; kt < 4; kt++) {
            uint4 bb[8];
#pragma unroll
            for (int nn = 0; nn < 8; nn++) {
                unsigned nb = (unsigned)(nn * 8 + rfrag) * SW2_STRIDE + (unsigned)kt * 64 + (unsigned)tg * 16;
                bb[nn] = *(const uint4*)(smem + wb + nb);
            }
#pragma unroll
            for (int nn = 0; nn < 8; nn++) {
                unsigned bh[2] = {bb[nn].x, bb[nn].y};
                mma_bf16(acc2[nn], gh[kt], bh);
            }
#pragma unroll
            for (int nn = 0; nn < 8; nn++) {
                unsigned bh[2] = {bb[nn].x, bb[nn].y};
                mma_bf16(acc2[nn], gl[kt], bh);
            }
#pragma unroll
            for (int nn = 0; nn < 8; nn++) {
                unsigned bl[2] = {bb[nn].z, bb[nn].w};
                mma_bf16(acc2[nn], gh[kt], bl);
            }
        }

        if (c == 0) {
            // residual: dst[b][oc][ta] = acc + b_res[oc] + x_tap1 (reconstructed from A smem)
#pragma unroll
            for (int nn = 0; nn < 8; nn++) {
                int oc = nn * 8 + 2 * tg;
                unsigned e = (unsigned)oc & 15;
                unsigned colOff = (4u + ((unsigned)oc >> 4)) * 64 + ((e & 7) >> 1) * 16 + (e >> 3) * 4;
#pragma unroll
                for (int h = 0; h < 2; h++) {
                    int rr = w * 16 + rfrag + 8 * h;
                    int ta = t0 + rr;
                    if (ta >= 0) {
                        unsigned off = (unsigned)rr * SA_STRIDE + colOff;
                        unsigned xh = *(const unsigned*)(smem + OFF_A + off);
                        unsigned xl = *(const unsigned*)(smem + OFF_A + off + 8);
                        float x0 = __uint_as_float(xh << 16) + __uint_as_float(xl << 16);
                        float x1 = __uint_as_float(xh & 0xffff0000u) + __uint_as_float(xl & 0xffff0000u);
                        float v0 = acc2[nn][2 * h] + sBias[oc] + x0;
                        float v1 = acc2[nn][2 * h + 1] + sBias[oc + 1] + x1;
                        dst[(size_t)(b * 64 + oc) * 8192 + ta] = v0;
                        dst[(size_t)(b * 64 + oc + 1) * 8192 + ta] = v1;
                    }
                }
            }
        } else {
#pragma unroll
            for (int nn = 0; nn < 8; nn++) {
                int cs = (c - 1) * 64 + nn * 8 + 2 * tg;
#pragma unroll
                for (int h = 0; h < 2; h++) {
                    int rr = w * 16 + rfrag + 8 * h;
                    int s = t0 + rr - skipOff;
                    if (s >= 0) {
                        float v0 = acc2[nn][2 * h] + sBias[64 + cs];
                        float v1 = acc2[nn][2 * h + 1] + sBias[64 + cs + 1];
                        skipOut[((size_t)b * 128 + cs) * 4096 + s] = v0;
                        skipOut[((size_t)b * 128 + cs + 1) * 4096 + s] = v1;
                    }
                }
            }
        }
    }
}

// ------------------------- launch -------------------------
extern "C" void kernel_launch(void* const* d_in, const int* in_sizes, int n_in,
                              void* d_out, int out_size) {
    const float* x      = (const float*)d_in[0];
    const float* w_dil  = (const float*)d_in[1];
    const float* w_res  = (const float*)d_in[2];
    const float* b_res  = (const float*)d_in[3];
    const float* w_skip = (const float*)d_in[4];
    const float* b_skip = (const float*)d_in[5];
    float* out = (float*)d_out;
    (void)in_sizes; (void)n_in; (void)out_size;

    cudaFuncSetAttribute(layer_kernel, cudaFuncAttributeMaxDynamicSharedMemorySize, SMEM_BYTES);

    float *bufA, *bufB, *biasP;
    unsigned char *w1P, *w2P;
    cudaGetSymbolAddress((void**)&bufA, g_buf0);
    cudaGetSymbolAddress((void**)&bufB, g_buf1);
    cudaGetSymbolAddress((void**)&w1P, g_w1img);
    cudaGetSymbolAddress((void**)&w2P, g_w2img);
    cudaGetSymbolAddress((void**)&biasP, g_bias);

    repack_kernel<<<(RNTOT + 255) / 256, 256>>>(w_dil, w_res, b_res, w_skip, b_skip);

    int T = 8192;
    const float* src = x;
    for (int l = 0; l < NLAYERS; l++) {
        int d = 1 << (l % 10);
        int L = T - d;
        float* dst = (l & 1) ? bufB : bufA;
        int nTiles = (L + TB - 1) / TB;
        dim3 grid(nTiles, 8);
        layer_kernel<<<grid, NT, SMEM_BYTES>>>(
            src, dst,
            w1P + (size_t)l * W1_BYTES, w2P + (size_t)l * W2_BYTES, biasP + (size_t)l * 192,
            out + (size_t)l * 8 * 128 * 4096, d, L, nTiles);
        src = dst;
        T = L;
    }
}

// round 17
// speedup vs baseline: 1.1804x; 1.1804x over previous
#include <cuda_runtime.h>
#include <cuda_bf16.h>
#include <math.h>

#define NLAYERS 40
#define TB 128
#define NT 256

// padded strides: stride(bytes) % 128 == 32 -> conflict-free 8B fragment loads
#define SA_STRIDE 288      // A rows: 256B data + 32 pad
#define SW1_STRIDE 288     // W1 rows: 256B data + 32 pad
#define SW2_STRIDE 160     // W2 rows: 128B data + 32 pad

// smem layout (bytes)
#define OFF_A_HI 0                  // 128*288 = 36864
#define OFF_A_LO 36864              // 36864
#define OFF_W    73728              // weight hi region (20480)
#define OFF_WLO  94208              // weight lo region (20480)
#define OFF_BIAS 114688             // 192 f32
#define SMEM_BYTES 115456

#define W1_BYTES 36864              // hi 18432 | lo 18432
#define W2_BYTES 61440              // hi 30720 | lo 30720 (192 rows * 160)

// ---------------- global scratch ----------------
__device__ float g_buf0[8 * 64 * 8192];
__device__ float g_buf1[8 * 64 * 8192];
__device__ __align__(16) unsigned char g_w1img[NLAYERS * W1_BYTES];
__device__ __align__(16) unsigned char g_w2img[NLAYERS * W2_BYTES];
__device__ float g_bias[NLAYERS * 192];

// ---------------- helpers ----------------
__device__ __forceinline__ unsigned smem_u32(const void* p) {
    unsigned a;
    asm("{ .reg .u64 t; cvta.to.shared.u64 t, %1; cvt.u32.u64 %0, t; }" : "=r"(a) : "l"(p));
    return a;
}
__device__ __forceinline__ void cp16(unsigned saddr, const void* g) {
    asm volatile("cp.async.cg.shared.global [%0], [%1], 16;" :: "r"(saddr), "l"(g) : "memory");
}
#define CP_COMMIT() asm volatile("cp.async.commit_group;" ::: "memory")
#define CP_WAIT0()  asm volatile("cp.async.wait_group 0;" ::: "memory")

__device__ __forceinline__ void mma_bf16(float* c, const unsigned* a, const unsigned* b) {
    asm volatile(
        "mma.sync.aligned.m16n8k16.row.col.f32.bf16.bf16.f32 "
        "{%0,%1,%2,%3}, {%4,%5,%6,%7}, {%8,%9}, {%0,%1,%2,%3};"
        : "+f"(c[0]), "+f"(c[1]), "+f"(c[2]), "+f"(c[3])
        : "r"(a[0]), "r"(a[1]), "r"(a[2]), "r"(a[3]), "r"(b[0]), "r"(b[1]));
}

__device__ __forceinline__ void split2(float a, float b, unsigned& hi, unsigned& lo) {
    __nv_bfloat16 ha = __float2bfloat16(a), hb = __float2bfloat16(b);
    float la = a - __bfloat162float(ha);
    float lb = b - __bfloat162float(hb);
    hi = ((unsigned)__bfloat16_as_ushort(hb) << 16) | (unsigned)__bfloat16_as_ushort(ha);
    __nv_bfloat16 bla = __float2bfloat16(la), blb = __float2bfloat16(lb);
    lo = ((unsigned)__bfloat16_as_ushort(blb) << 16) | (unsigned)__bfloat16_as_ushort(bla);
}

__device__ __forceinline__ float gate_fn(float y) {
    float ay = fabsf(y);
    float e1 = __expf(-ay);
    float e2 = e1 * e1;
    float th = __fdividef(1.f - e2, 1.f + e2);
    float sp = __fdividef(1.f, 1.f + e1);
    float sig = (y >= 0.f) ? sp : (1.f - sp);
    return copysignf(th, y) * sig;
}

// ------------------------- weight repack (vectorized: thread = one 32B chunk) -------------------------
// chunk word layout (matches kernel fragment loads): word[2j]=pack(e2j,e2j+1), word[2j+1]=pack(e2j+8,e2j+9)
#define RP_W1 (NLAYERS * 64 * 8)      // 20480
#define RP_W2 (NLAYERS * 192 * 4)     // 30720
#define RP_B1 (NLAYERS * 64)
#define RP_B2 (NLAYERS * 128)
#define RP_TOT (RP_W1 + RP_W2 + RP_B1 + RP_B2)

__global__ void repack_kernel(const float* __restrict__ wd, const float* __restrict__ wr,
                              const float* __restrict__ br, const float* __restrict__ ws,
                              const float* __restrict__ bs) {
    int idx = blockIdx.x * blockDim.x + threadIdx.x;
    if (idx < RP_W1) {  // W1: (l, o, c) ; col = c*16+e ; k=col>>6 ; i=col&63
        int c = idx & 7, o = (idx >> 3) & 63, l = idx >> 9;
        const float* base = wd + (size_t)l * 8192 + o * 128 + (c & 3) * 32 + (c >> 2);
        float v[16];
#pragma unroll
        for (int e = 0; e < 16; e++) v[e] = base[e * 2];
        unsigned hw[8], lw[8];
#pragma unroll
        for (int j = 0; j < 4; j++) {
            split2(v[2 * j], v[2 * j + 1], hw[2 * j], lw[2 * j]);
            split2(v[2 * j + 8], v[2 * j + 9], hw[2 * j + 1], lw[2 * j + 1]);
        }
        unsigned char* dh = g_w1img + (size_t)l * W1_BYTES + o * SW1_STRIDE + c * 32;
        *(uint4*)dh = make_uint4(hw[0], hw[1], hw[2], hw[3]);
        *(uint4*)(dh + 16) = make_uint4(hw[4], hw[5], hw[6], hw[7]);
        unsigned char* dl = dh + 18432;
        *(uint4*)dl = make_uint4(lw[0], lw[1], lw[2], lw[3]);
        *(uint4*)(dl + 16) = make_uint4(lw[4], lw[5], lw[6], lw[7]);
        return;
    }
    idx -= RP_W1;
    if (idx < RP_W2) {  // W2: (l, r, c); r<64: res row, else skip row r-64
        int c = idx & 3;
        int t = idx >> 2;
        int r = t % 192;
        int l = t / 192;
        const float* base = (r < 64) ? (wr + (size_t)l * 4096 + r * 64 + c * 16)
                                     : (ws + (size_t)l * 8192 + (r - 64) * 64 + c * 16);
        float v[16];
#pragma unroll
        for (int e = 0; e < 16; e++) v[e] = base[e];
        unsigned hw[8], lw[8];
#pragma unroll
        for (int j = 0; j < 4; j++) {
            split2(v[2 * j], v[2 * j + 1], hw[2 * j], lw[2 * j]);
            split2(v[2 * j + 8], v[2 * j + 9], hw[2 * j + 1], lw[2 * j + 1]);
        }
        unsigned char* dh = g_w2img + (size_t)l * W2_BYTES + r * SW2_STRIDE + c * 32;
        *(uint4*)dh = make_uint4(hw[0], hw[1], hw[2], hw[3]);
        *(uint4*)(dh + 16) = make_uint4(hw[4], hw[5], hw[6], hw[7]);
        unsigned char* dl = dh + 30720;
        *(uint4*)dl = make_uint4(lw[0], lw[1], lw[2], lw[3]);
        *(uint4*)(dl + 16) = make_uint4(lw[4], lw[5], lw[6], lw[7]);
        return;
    }
    idx -= RP_W2;
    if (idx < RP_B1) { int o = idx & 63, l = idx >> 6; g_bias[l * 192 + o] = br[idx]; return; }
    idx -= RP_B1;
    if (idx < RP_B2) { int o = idx & 127, l = idx >> 7; g_bias[l * 192 + 64 + o] = bs[idx]; return; }
}

// ------------------------- phase-2 MMA block -------------------------
__device__ __forceinline__ void p2_mma(const unsigned char* smem, unsigned wb, unsigned wlb,
                                       const unsigned gh[4][4], const unsigned gl[4][4],
                                       int rfrag, int tg, float acc2[8][4]) {
#pragma unroll
    for (int nn = 0; nn < 8; nn++)
#pragma unroll
        for (int q = 0; q < 4; q++) acc2[nn][q] = 0.f;
#pragma unroll 2
    for (int kt = 0; kt < 4; kt++) {
#pragma unroll
        for (int nn = 0; nn < 8; nn++) {
            unsigned nb = (unsigned)(nn * 8 + rfrag) * SW2_STRIDE + (unsigned)kt * 32 + (unsigned)tg * 8;
            uint2 bhv = *(const uint2*)(smem + wb + nb);
            uint2 blv = *(const uint2*)(smem + wlb + nb);
            unsigned bh[2] = {bhv.x, bhv.y};
            unsigned bl[2] = {blv.x, blv.y};
            mma_bf16(acc2[nn], gh[kt], bh);
            mma_bf16(acc2[nn], gl[kt], bh);
            mma_bf16(acc2[nn], gh[kt], bl);
        }
    }
}

// ------------------------- fused mma.sync layer kernel -------------------------
// CTA: 128 timesteps x one batch. 8 warps; warp w owns rows 16w..16w+15.
__global__ __launch_bounds__(NT, 2) void layer_kernel(
    const float* __restrict__ src, float* __restrict__ dst,
    const unsigned char* __restrict__ w1img, const unsigned char* __restrict__ w2img,
    const float* __restrict__ bias, float* __restrict__ skipOut,
    int d, int L, int nTiles) {
    extern __shared__ unsigned char smem[];
    const unsigned sb = smem_u32(smem);
    const int tid = threadIdx.x;
    const int lane = tid & 31;
    const int w = tid >> 5;
    const int b = blockIdx.y;
    const int t0 = L - (nTiles - blockIdx.x) * TB;
    const int Tin = L + d;

    // ---- W1 via cp.async (2304 u4: hi then lo, gmem-contiguous) + bias ----
    {
#pragma unroll
        for (int k = 0; k < 9; k++) {
            int i = tid + NT * k;
            unsigned dstOff = ((i < 1152) ? (unsigned)OFF_W : (unsigned)(OFF_W + 2048)) + (unsigned)i * 16;
            cp16(sb + dstOff, w1img + (size_t)i * 16);
        }
        CP_COMMIT();
        float* sBias = (float*)(smem + OFF_BIAS);
        if (tid < 192) sBias[tid] = bias[tid];
    }

    // ---- stage A: thread = (row, tap). Coalesced gmem loads, bf16 hi/lo scatter ----
    const float* srcB = src + (size_t)b * 64 * 8192;
    {
        const int row = tid & 127;
        const int tap = tid >> 7;
        const int sh = tap ? d : 0;
        int g = t0 + row + sh;
        g = min(max(g, 0), Tin - 1);
        const float* colp = srcB + g;
        unsigned rowb = (unsigned)row * SA_STRIDE;
#pragma unroll
        for (int cc = 0; cc < 4; cc++) {
            float v[16];
#pragma unroll
            for (int e = 0; e < 16; e++) v[e] = colp[(size_t)(cc * 16 + e) * 8192];
            unsigned addr0 = rowb + (unsigned)(tap * 4 + cc) * 32;
#pragma unroll
            for (int hh = 0; hh < 2; hh++) {
                unsigned h[4], l[4];
                split2(v[4 * hh + 0], v[4 * hh + 1], h[0], l[0]);
                split2(v[4 * hh + 8], v[4 * hh + 9], h[1], l[1]);
                split2(v[4 * hh + 2], v[4 * hh + 3], h[2], l[2]);
                split2(v[4 * hh + 10], v[4 * hh + 11], h[3], l[3]);
                unsigned a = addr0 + hh * 16;
                *(uint4*)(smem + OFF_A_HI + a) = make_uint4(h[0], h[1], h[2], h[3]);
                *(uint4*)(smem + OFF_A_LO + a) = make_uint4(l[0], l[1], l[2], l[3]);
            }
        }
    }
    CP_WAIT0();
    __syncthreads();

    const int tg = lane & 3;
    const int rfrag = lane >> 2;

    // ---------------- phase 1: y = A @ W1^T (3-split bf16) ----------------
    float acc[8][4];
#pragma unroll
    for (int nn = 0; nn < 8; nn++)
#pragma unroll
        for (int q = 0; q < 4; q++) acc[nn][q] = 0.f;

#pragma unroll 2
    for (int kk = 0; kk < 8; kk++) {
        unsigned ra = (unsigned)(w * 16 + rfrag) * SA_STRIDE + (unsigned)kk * 32 + (unsigned)tg * 8;
        uint2 uh = *(const uint2*)(smem + OFF_A_HI + ra);
        uint2 vh = *(const uint2*)(smem + OFF_A_HI + ra + 8 * SA_STRIDE);
        uint2 ul = *(const uint2*)(smem + OFF_A_LO + ra);
        uint2 vl = *(const uint2*)(smem + OFF_A_LO + ra + 8 * SA_STRIDE);
        unsigned ah[4] = {uh.x, vh.x, uh.y, vh.y};
        unsigned al[4] = {ul.x, vl.x, ul.y, vl.y};
#pragma unroll
        for (int nn = 0; nn < 8; nn++) {
            unsigned nb = (unsigned)(nn * 8 + rfrag) * SW1_STRIDE + (unsigned)kk * 32 + (unsigned)tg * 8;
            uint2 bhv = *(const uint2*)(smem + OFF_W + nb);
            uint2 blv = *(const uint2*)(smem + OFF_WLO + nb);
            unsigned bh[2] = {bhv.x, bhv.y};
            unsigned bl[2] = {blv.x, blv.y};
            mma_bf16(acc[nn], ah, bh);
            mma_bf16(acc[nn], al, bh);
            mma_bf16(acc[nn], ah, bl);
        }
    }

    // ---- prefetch W2 chunks 0(,1) while computing gate fragments ----
    __syncthreads();   // all warps done reading W1 region
    const int skipOff = L - 4096;
    const bool needSkip = (t0 + TB > skipOff);
    {
        int n = needSkip ? 1280 : 640;
        for (int i = tid; i < n; i += NT) {
            cp16(sb + OFF_W + (unsigned)i * 16, w2img + (size_t)i * 16);
            cp16(sb + OFF_WLO + (unsigned)i * 16, w2img + 30720 + (size_t)i * 16);
        }
        CP_COMMIT();
    }

    // gate -> phase2 A fragments (registers only)
    unsigned gh[4][4], gl[4][4];
#pragma unroll
    for (int kt = 0; kt < 4; kt++) {
        int n0 = 2 * kt, n1 = 2 * kt + 1;
        split2(gate_fn(acc[n0][0]), gate_fn(acc[n0][1]), gh[kt][0], gl[kt][0]);
        split2(gate_fn(acc[n0][2]), gate_fn(acc[n0][3]), gh[kt][1], gl[kt][1]);
        split2(gate_fn(acc[n1][0]), gate_fn(acc[n1][1]), gh[kt][2], gl[kt][2]);
        split2(gate_fn(acc[n1][2]), gate_fn(acc[n1][3]), gh[kt][3], gl[kt][3]);
    }
    CP_WAIT0();
    __syncthreads();

    const float* sBias = (const float*)(smem + OFF_BIAS);
    float acc2[8][4];

    // ---------------- c0: residual GEMM ----------------
    p2_mma(smem, OFF_W, OFF_WLO, gh, gl, rfrag, tg, acc2);

    // prefetch chunk 2 into chunk-0 slot while doing c0 epilogue + c1
    if (needSkip) {
        __syncthreads();   // all warps done reading chunk-0 weights
        for (int i = tid; i < 640; i += NT) {
            cp16(sb + OFF_W + (unsigned)i * 16, w2img + 20480 + (size_t)i * 16);
            cp16(sb + OFF_WLO + (unsigned)i * 16, w2img + 51200 + (size_t)i * 16);
        }
        CP_COMMIT();
    }

    // c0 epilogue: residual store (x_tap1 reconstructed from A smem)
#pragma unroll
    for (int nn = 0; nn < 8; nn++) {
        int oc = nn * 8 + 2 * tg;
        unsigned q = ((unsigned)oc & 15) >> 1;
        unsigned colOff = (4u + ((unsigned)oc >> 4)) * 32 + (q & 3) * 8 + (q >> 2) * 4;
#pragma unroll
        for (int h = 0; h < 2; h++) {
            int rr = w * 16 + rfrag + 8 * h;
            int ta = t0 + rr;
            if (ta >= 0) {
                unsigned off = (unsigned)rr * SA_STRIDE + colOff;
                unsigned xh = *(const unsigned*)(smem + OFF_A_HI + off);
                unsigned xl = *(const unsigned*)(smem + OFF_A_LO + off);
                float x0 = __uint_as_float(xh << 16) + __uint_as_float(xl << 16);
                float x1 = __uint_as_float(xh & 0xffff0000u) + __uint_as_float(xl & 0xffff0000u);
                float v0 = acc2[nn][2 * h] + sBias[oc] + x0;
                float v1 = acc2[nn][2 * h + 1] + sBias[oc + 1] + x1;
                dst[(size_t)(b * 64 + oc) * 8192 + ta] = v0;
                dst[(size_t)(b * 64 + oc + 1) * 8192 + ta] = v1;
            }
        }
    }

    if (needSkip) {
        // ---------------- c1: skip channels 0..63 (chunk 1, untouched slot) ----------------
        p2_mma(smem, OFF_W + 10240, OFF_WLO + 10240, gh, gl, rfrag, tg, acc2);
#pragma unroll
        for (int nn = 0; nn < 8; nn++) {
            int cs = nn * 8 + 2 * tg;
#pragma unroll
            for (int h = 0; h < 2; h++) {
                int rr = w * 16 + rfrag + 8 * h;
                int s = t0 + rr - skipOff;
                if (s >= 0) {
                    skipOut[((size_t)b * 128 + cs) * 4096 + s] = acc2[nn][2 * h] + sBias[64 + cs];
                    skipOut[((size_t)b * 128 + cs + 1) * 4096 + s] = acc2[nn][2 * h + 1] + sBias[64 + cs + 1];
                }
            }
        }

        // ---------------- c2: skip channels 64..127 (prefetched into chunk-0 slot) ----------------
        CP_WAIT0();
        __syncthreads();
        p2_mma(smem, OFF_W, OFF_WLO, gh, gl, rfrag, tg, acc2);
#pragma unroll
        for (int nn = 0; nn < 8; nn++) {
            int cs = 64 + nn * 8 + 2 * tg;
#pragma unroll
            for (int h = 0; h < 2; h++) {
                int rr = w * 16 + rfrag + 8 * h;
                int s = t0 + rr - skipOff;
                if (s >= 0) {
                    skipOut[((size_t)b * 128 + cs) * 4096 + s] = acc2[nn][2 * h] + sBias[64 + cs];
                    skipOut[((size_t)b * 128 + cs + 1) * 4096 + s] = acc2[nn][2 * h + 1] + sBias[64 + cs + 1];
                }
            }
        }
    }
}

// ------------------------- launch -------------------------
extern "C" void kernel_launch(void* const* d_in, const int* in_sizes, int n_in,
                              void* d_out, int out_size) {
    const float* x      = (const float*)d_in[0];
    const float* w_dil  = (const float*)d_in[1];
    const float* w_res  = (const float*)d_in[2];
    const float* b_res  = (const float*)d_in[3];
    const float* w_skip = (const float*)d_in[4];
    const float* b_skip = (const float*)d_in[5];
    float* out = (float*)d_out;
    (void)in_sizes; (void)n_in; (void)out_size;

    cudaFuncSetAttribute(layer_kernel, cudaFuncAttributeMaxDynamicSharedMemorySize, SMEM_BYTES);

    float *bufA, *bufB, *biasP;
    unsigned char *w1P, *w2P;
    cudaGetSymbolAddress((void**)&bufA, g_buf0);
    cudaGetSymbolAddress((void**)&bufB, g_buf1);
    cudaGetSymbolAddress((void**)&w1P, g_w1img);
    cudaGetSymbolAddress((void**)&w2P, g_w2img);
    cudaGetSymbolAddress((void**)&biasP, g_bias);

    repack_kernel<<<(RP_TOT + 255) / 256, 256>>>(w_dil, w_res, b_res, w_skip, b_skip);

    int T = 8192;
    const float* src = x;
    for (int l = 0; l < NLAYERS; l++) {
        int d = 1 << (l % 10);
        int L = T - d;
        float* dst = (l & 1) ? bufB : bufA;
        int nTiles = (L + TB - 1) / TB;
        dim3 grid(nTiles, 8);
        layer_kernel<<<grid, NT, SMEM_BYTES>>>(
            src, dst,
            w1P + (size_t)l * W1_BYTES, w2P + (size_t)l * W2_BYTES, biasP + (size_t)l * 192,
            out + (size_t)l * 8 * 128 * 4096, d, L, nTiles);
        src = dst;
        T = L;
    }
}